// round 5
// baseline (speedup 1.0000x reference)
#include <cuda_runtime.h>
#include <cstddef>

#define B_  16
#define C_  1024
#define T_  16
#define HW_ 360      // H*W = 12*30
#define K_  120
#define ROWS_ 482    // 1 + 120 + 1 + 360
#define CHUNKS 64
#define CC 16        // channels per chunk (CHUNKS*CC == C_)
#define STRIDE_T (T_*HW_)   // 5760 floats between consecutive c for fixed (b,t,p)

// Scratch (no allocations allowed in kernel_launch)
__device__ float g_partial[B_][CHUNKS][HW_];
__device__ int   g_topk[B_][K_];

// ---------------------------------------------------------------------------
// K1: partial dot products  d[b,p] += sum_{c in chunk} cls[b,0,c] * x[b,c,0,p]
// grid (CHUNKS=64, B) = 1024 blocks, 192 threads (180 active lanes own two
// p's each via float2). fp32 FFMA, two paired accumulators. High block count
// gives the MLP needed to cover DRAM latency.
// ---------------------------------------------------------------------------
__global__ void scores_kernel(const float* __restrict__ x,
                              const float* __restrict__ cls) {
    const int chunk = blockIdx.x;
    const int b     = blockIdx.y;
    const int tid   = threadIdx.x;

    __shared__ float cls_s[CC];
    if (tid < CC)
        cls_s[tid] = cls[(size_t)b * T_ * C_ + (size_t)chunk * CC + tid];  // t = 0
    __syncthreads();

    if (tid >= HW_ / 2) return;   // 180 active lanes, p = 2*tid, 2*tid+1

    const float2* xr = (const float2*)(x + ((size_t)(b * C_ + chunk * CC)) * STRIDE_T) + tid;
    const size_t cstride2 = STRIDE_T / 2;   // 2880 float2 between c rows

    float2 a0 = make_float2(0.f, 0.f);
    float2 a1 = make_float2(0.f, 0.f);
#pragma unroll
    for (int j = 0; j < CC; j += 2) {
        const float2 v0 = xr[(size_t)j       * cstride2];
        const float2 v1 = xr[(size_t)(j + 1) * cstride2];
        const float  w0 = cls_s[j];
        const float  w1 = cls_s[j + 1];
        a0.x = fmaf(w0, v0.x, a0.x);
        a0.y = fmaf(w0, v0.y, a0.y);
        a1.x = fmaf(w1, v1.x, a1.x);
        a1.y = fmaf(w1, v1.y, a1.y);
    }

    g_partial[b][chunk][2 * tid]     = a0.x + a1.x;
    g_partial[b][chunk][2 * tid + 1] = a0.y + a1.y;
}

// ---------------------------------------------------------------------------
// K2: per-batch chunk reduction (deterministic order, double), bitonic top-K
// of 512 (value descending, index ascending — matches jax.lax.top_k), plus
// the two cls rows of the output.  grid (B), 256 threads.
// ---------------------------------------------------------------------------
__global__ void topk_kernel(const float* __restrict__ cls,
                            float* __restrict__ out) {
    const int b   = blockIdx.x;
    const int tid = threadIdx.x;

    __shared__ double sval[512];
    __shared__ int    sidx[512];

    for (int i = tid; i < 512; i += 256) {
        double s;
        if (i < HW_) {
            s = 0.0;
#pragma unroll 8
            for (int j = 0; j < CHUNKS; ++j) s += (double)g_partial[b][j][i];
        } else {
            s = -1e300;   // pad below any real score
        }
        sval[i] = s;
        sidx[i] = i;
    }
    __syncthreads();

    // Bitonic sort, 512 elements, key order = (value desc, index asc)
    for (int k = 2; k <= 512; k <<= 1) {
        for (int j = k >> 1; j > 0; j >>= 1) {
            for (int i = tid; i < 512; i += 256) {
                const int ixj = i ^ j;
                if (ixj > i) {
                    const double v1 = sval[i], v2 = sval[ixj];
                    const int    i1 = sidx[i], i2 = sidx[ixj];
                    const bool iFirst = (v1 > v2) || (v1 == v2 && i1 < i2);
                    const bool up = ((i & k) == 0);
                    if (up != iFirst) {
                        sval[i] = v2; sval[ixj] = v1;
                        sidx[i] = i2; sidx[ixj] = i1;
                    }
                }
            }
            __syncthreads();
        }
    }

    if (tid < K_) g_topk[b][tid] = sidx[tid];

    // cls rows: out row 0 = cls[b,0,:], out row 121 = cls[b,1,:]
    for (int c = tid; c < C_; c += 256) {
        out[((size_t)b * ROWS_ + 0)   * C_ + c] = cls[(size_t)b * T_ * C_ + c];
        out[((size_t)b * ROWS_ + 121) * C_ + c] = cls[(size_t)b * T_ * C_ + C_ + c];
    }
}

// ---------------------------------------------------------------------------
// K3: tile-and-select assemble.
// grid (32 c-tiles, B, 2), block 256.
//   z=0: load full 32x360 t=0 slice coalesced into smem, write the 120
//        selected columns transposed -> out rows 1..120.
//   z=1: same for the t=1 slice, write all 360 columns -> out rows 122..481.
// Every global read is a contiguous row stream (no scattered gather);
// smem pitch 361 (odd) makes the strided transpose reads conflict-free.
// ---------------------------------------------------------------------------
__global__ void assemble_kernel(const float* __restrict__ x,
                                float* __restrict__ out) {
    const int ct = blockIdx.x;           // c tile (32 channels)
    const int b  = blockIdx.y;
    const int z  = blockIdx.z;           // 0: t=0 gather, 1: t=1 copy
    const int tid = threadIdx.x;
    const int c0 = ct * 32;

    __shared__ float tile[32][361];
    __shared__ int   pidx[K_];

    const float* base = x + ((size_t)(b * C_ + c0)) * STRIDE_T + (z ? HW_ : 0);

    // coalesced load of 32 channel rows x 360 patches
    for (int idx = tid; idx < 32 * HW_; idx += 256) {
        const int r   = idx / HW_;
        const int col = idx - r * HW_;
        tile[r][col] = base[(size_t)r * STRIDE_T + col];
    }
    if (z == 0)
        for (int i = tid; i < K_; i += 256) pidx[i] = g_topk[b][i];
    __syncthreads();

    const int lane = tid & 31;
    const int wrow = tid >> 5;           // 0..7

    if (z == 0) {
        for (int k = wrow; k < K_; k += 8) {
            const int p = pidx[k];
            out[((size_t)b * ROWS_ + 1 + k) * C_ + c0 + lane] = tile[lane][p];
        }
    } else {
        for (int p = wrow; p < HW_; p += 8) {
            out[((size_t)b * ROWS_ + 122 + p) * C_ + c0 + lane] = tile[lane][p];
        }
    }
}

// ---------------------------------------------------------------------------
extern "C" void kernel_launch(void* const* d_in, const int* in_sizes, int n_in,
                              void* d_out, int out_size) {
    const float* x   = (const float*)d_in[0];
    const float* cls = (const float*)d_in[1];
    // Defensive: x is the huge tensor (94,371,840 elems), cls is 262,144.
    if (n_in >= 2 && in_sizes[0] < in_sizes[1]) {
        const float* tmp = x; x = cls; cls = tmp;
    }
    float* out = (float*)d_out;

    scores_kernel  <<<dim3(CHUNKS, B_), 192>>>(x, cls);
    topk_kernel    <<<B_, 256>>>(cls, out);
    assemble_kernel<<<dim3(32, B_, 2), 256>>>(x, out);
}

// round 7
// speedup vs baseline: 1.1611x; 1.1611x over previous
#include <cuda_runtime.h>
#include <cstddef>

#define B_  16
#define C_  1024
#define T_  16
#define HW_ 360      // H*W = 12*30
#define K_  120
#define ROWS_ 482    // 1 + 120 + 1 + 360
#define CHUNKS 32    // 32 channels per chunk
#define STRIDE_T (T_*HW_)   // 5760 floats between consecutive c for fixed (b,t,p)

// Scratch (no allocations allowed in kernel_launch)
__device__ float4 g_partial4[B_][CHUNKS][HW_/4];   // [b][chunk][90] float4 == 360 floats
__device__ int    g_topk[B_][K_];

// ---------------------------------------------------------------------------
// K1: partial dot products. grid (CHUNKS=32, B), block 384 (360 active).
// Thread t<360: p4 = t%90 (4 p's via float4), cg = t/90 (8-channel group;
// 4 groups x 8 = 32 channels/chunk). 8 independent float4 loads per thread
// (real MLP), deterministic fixed-order reduce across the 4 groups via smem.
// ---------------------------------------------------------------------------
__global__ void scores_kernel(const float* __restrict__ x,
                              const float* __restrict__ cls) {
    const int chunk = blockIdx.x;
    const int b     = blockIdx.y;
    const int tid   = threadIdx.x;

    __shared__ float  cls_s[32];
    __shared__ float4 red[360];          // [cg*90 + p4]

    if (tid < 32)
        cls_s[tid] = cls[(size_t)b * T_ * C_ + (size_t)chunk * 32 + tid];  // t=0
    __syncthreads();

    if (tid < 360) {
        const int p4 = tid % 90;
        const int cg = tid / 90;

        const float* base = x + ((size_t)(b * C_ + chunk * 32 + cg * 8)) * STRIDE_T + 4 * p4;

        float4 v[8];
#pragma unroll
        for (int j = 0; j < 8; ++j)
            v[j] = *(const float4*)(base + (size_t)j * STRIDE_T);

        float4 acc = make_float4(0.f, 0.f, 0.f, 0.f);
#pragma unroll
        for (int j = 0; j < 8; ++j) {
            const float w = cls_s[cg * 8 + j];
            acc.x = fmaf(w, v[j].x, acc.x);
            acc.y = fmaf(w, v[j].y, acc.y);
            acc.z = fmaf(w, v[j].z, acc.z);
            acc.w = fmaf(w, v[j].w, acc.w);
        }
        red[cg * 90 + p4] = acc;
    }
    __syncthreads();

    if (tid < 90) {
        const float4 a = red[tid];
        const float4 b1 = red[90 + tid];
        const float4 c = red[180 + tid];
        const float4 d = red[270 + tid];
        float4 s;
        s.x = ((a.x + b1.x) + c.x) + d.x;
        s.y = ((a.y + b1.y) + c.y) + d.y;
        s.z = ((a.z + b1.z) + c.z) + d.z;
        s.w = ((a.w + b1.w) + c.w) + d.w;
        g_partial4[b][chunk][tid] = s;
    }
}

// ---------------------------------------------------------------------------
// K2: per-batch reduce (32 chunks, double, fixed order) + bitonic sort of 512
// with one element per thread (shfl for j<32: 35 of 45 phases barrier-free).
// Key order: value desc, index asc (jax.lax.top_k semantics).
// Also writes the two cls rows of the output. grid (B), 512 threads.
// ---------------------------------------------------------------------------
__global__ void topk_kernel(const float* __restrict__ cls,
                            float* __restrict__ out) {
    const int b   = blockIdx.x;
    const int tid = threadIdx.x;

    __shared__ double sv[512];
    __shared__ int    si[512];

    double v;
    int    idx = tid;
    if (tid < HW_) {
        const float* gp = (const float*)&g_partial4[b][0][0];
        double s = 0.0;
#pragma unroll 8
        for (int j = 0; j < CHUNKS; ++j) s += (double)gp[j * HW_ + tid];
        v = s;
    } else {
        v = -1e300;
    }

    for (int k = 2; k <= 512; k <<= 1) {
        const bool up = ((tid & k) == 0);
        int j = k >> 1;
        for (; j >= 32; j >>= 1) {
            sv[tid] = v; si[tid] = idx;
            __syncthreads();
            const double pv = sv[tid ^ j];
            const int    pi = si[tid ^ j];
            __syncthreads();
            const bool iLess = (v > pv) || (v == pv && idx < pi);
            const bool lower = ((tid & j) == 0);
            const bool keepOwn = lower ? (up ? iLess : !iLess)
                                       : (up ? !iLess : iLess);
            if (!keepOwn) { v = pv; idx = pi; }
        }
        for (; j >= 1; j >>= 1) {
            const double pv = __shfl_xor_sync(0xffffffffu, v, j);
            const int    pi = __shfl_xor_sync(0xffffffffu, idx, j);
            const bool iLess = (v > pv) || (v == pv && idx < pi);
            const bool lower = ((tid & j) == 0);
            const bool keepOwn = lower ? (up ? iLess : !iLess)
                                       : (up ? !iLess : iLess);
            if (!keepOwn) { v = pv; idx = pi; }
        }
    }

    if (tid < K_) g_topk[b][tid] = idx;

    // cls rows via float4: row 0 = cls[b,0,:], row 121 = cls[b,1,:]
    {
        const float4* c4 = (const float4*)(cls + (size_t)b * T_ * C_);
        float4* o4 = (float4*)(out + (size_t)b * ROWS_ * C_);
        if (tid < 256)
            o4[tid] = c4[tid];                            // row 0
        else
            o4[(size_t)121 * (C_ / 4) + (tid - 256)] = c4[(C_ / 4) + (tid - 256)]; // row 121
    }
}

// ---------------------------------------------------------------------------
// K3: assemble. grid (8 ctiles of 128 ch, 16 yt, B), block 256.
//   yt < 4 : gather tile (32 tokens): out[b,1+k,c] = x[b,c,0,topk[b][k]]
//            warp = one token, lanes sweep channels (conflict-free STS;
//            scattered 4B reads are L2-resident after K1).
//   yt >= 4: t=1 p-tile (32 patches): out[b,122+p,c] = x[b,c,1,p]
//            float4 coalesced loads along p, scalar STS (minor 4-way ok).
// tile[32][132]: pitch 132 (mult of 4, rows 16B-aligned) so the read phase
// can do float4 LDS (warp reads 512B contiguous -> conflict-free) and
// float4 coalesced STG to out.
// ---------------------------------------------------------------------------
__global__ void assemble_kernel(const float* __restrict__ x,
                                float* __restrict__ out) {
    const int ct  = blockIdx.x;          // 0..7  (128 channels each)
    const int yt  = blockIdx.y;          // 0..15
    const int b   = blockIdx.z;
    const int tid = threadIdx.x;         // 0..255
    const int c0  = ct * 128;
    const int lane = tid & 31;
    const int w    = tid >> 5;           // 0..7

    __shared__ __align__(16) float tile[32][132];
    __shared__ int pidx[32];

    if (yt < 4) {
        // ---------------- gather of top-K t=0 tokens ----------------
        const int k0 = yt * 32;
        if (tid < 32) {
            const int k = k0 + tid;
            pidx[tid] = (k < K_) ? g_topk[b][k] : 0;   // k>=120 masked on store
        }
        __syncthreads();

#pragma unroll
        for (int ii = 0; ii < 4; ++ii) {
            const int tok = w + 8 * ii;          // 0..31
            const int p   = pidx[tok];
            const float* src = x + ((size_t)(b * C_ + c0)) * STRIDE_T + p; // t=0
#pragma unroll
            for (int jj = 0; jj < 4; ++jj) {
                const int cl = lane + 32 * jj;   // 0..127
                tile[tok][cl] = src[(size_t)cl * STRIDE_T];
            }
        }
        __syncthreads();

#pragma unroll
        for (int i = 0; i < 4; ++i) {
            const int klocal = w + 8 * i;        // 0..31
            const int kr = k0 + klocal;
            if (kr < K_) {
                const float4 val = *(const float4*)&tile[klocal][4 * lane];
                *(float4*)&out[((size_t)b * ROWS_ + 1 + kr) * C_ + c0 + 4 * lane] = val;
            }
        }
    } else {
        // ---------------- t=1 slice transpose ----------------
        const int p0 = (yt - 4) * 32;            // 0,32,...,352 (last tile partial)
        const int p4 = tid & 7;                  // float4 index along p
        const int cb = tid >> 3;                 // 0..31
#pragma unroll
        for (int i = 0; i < 4; ++i) {
            const int cl = cb + 32 * i;          // 0..127
            const float4 val = *(const float4*)&x[((size_t)(b * C_ + c0 + cl)) * STRIDE_T
                                                  + HW_ + p0 + 4 * p4];
            tile[4 * p4 + 0][cl] = val.x;
            tile[4 * p4 + 1][cl] = val.y;
            tile[4 * p4 + 2][cl] = val.z;
            tile[4 * p4 + 3][cl] = val.w;
        }
        __syncthreads();

#pragma unroll
        for (int i = 0; i < 4; ++i) {
            const int plocal = w + 8 * i;        // 0..31
            const int pr = p0 + plocal;
            if (pr < HW_) {
                const float4 val = *(const float4*)&tile[plocal][4 * lane];
                *(float4*)&out[((size_t)b * ROWS_ + 122 + pr) * C_ + c0 + 4 * lane] = val;
            }
        }
    }
}

// ---------------------------------------------------------------------------
extern "C" void kernel_launch(void* const* d_in, const int* in_sizes, int n_in,
                              void* d_out, int out_size) {
    const float* x   = (const float*)d_in[0];
    const float* cls = (const float*)d_in[1];
    // Defensive: x is the huge tensor (94,371,840 elems), cls is 262,144.
    if (n_in >= 2 && in_sizes[0] < in_sizes[1]) {
        const float* tmp = x; x = cls; cls = tmp;
    }
    float* out = (float*)d_out;

    scores_kernel  <<<dim3(CHUNKS, B_), 384>>>(x, cls);
    topk_kernel    <<<B_, 512>>>(cls, out);
    assemble_kernel<<<dim3(8, 16, B_), 256>>>(x, out);
}

// round 8
// speedup vs baseline: 1.3102x; 1.1283x over previous
#include <cuda_runtime.h>
#include <cstddef>

#define B_  16
#define C_  1024
#define T_  16
#define HW_ 360      // H*W = 12*30
#define K_  120
#define ROWS_ 482    // 1 + 120 + 1 + 360
#define CHUNKS 32    // 32 channels per chunk
#define STRIDE_T (T_*HW_)   // 5760 floats between consecutive c for fixed (b,t,p)

// Scratch (no allocations allowed in kernel_launch)
__device__ float4 g_partial4[B_][CHUNKS][HW_/4];   // [b][chunk][90] float4 == 360 floats
__device__ int    g_topk[B_][K_];

// ---------------------------------------------------------------------------
// K1: partial dot products. grid (CHUNKS=32, B), block 384 (360 active).
// Thread t<360: p4 = t%90 (4 p's via float4), cg = t/90 (8-channel group).
// __launch_bounds__(384,2) raises the reg budget so ptxas keeps all 8
// float4 loads in flight (round-7 ran at 32 regs -> MLP collapsed).
// ---------------------------------------------------------------------------
__global__ void __launch_bounds__(384, 2)
scores_kernel(const float* __restrict__ x,
              const float* __restrict__ cls) {
    const int chunk = blockIdx.x;
    const int b     = blockIdx.y;
    const int tid   = threadIdx.x;

    __shared__ float  cls_s[32];
    __shared__ float4 red[360];          // [cg*90 + p4]

    if (tid < 32)
        cls_s[tid] = cls[(size_t)b * T_ * C_ + (size_t)chunk * 32 + tid];  // t=0
    __syncthreads();

    if (tid < 360) {
        const int p4 = tid % 90;
        const int cg = tid / 90;

        const float* base = x + ((size_t)(b * C_ + chunk * 32 + cg * 8)) * STRIDE_T + 4 * p4;

        float4 v[8];
#pragma unroll
        for (int j = 0; j < 8; ++j)
            v[j] = *(const float4*)(base + (size_t)j * STRIDE_T);

        float4 acc = make_float4(0.f, 0.f, 0.f, 0.f);
#pragma unroll
        for (int j = 0; j < 8; ++j) {
            const float w = cls_s[cg * 8 + j];
            acc.x = fmaf(w, v[j].x, acc.x);
            acc.y = fmaf(w, v[j].y, acc.y);
            acc.z = fmaf(w, v[j].z, acc.z);
            acc.w = fmaf(w, v[j].w, acc.w);
        }
        red[cg * 90 + p4] = acc;
    }
    __syncthreads();

    if (tid < 90) {
        const float4 a = red[tid];
        const float4 b1 = red[90 + tid];
        const float4 c = red[180 + tid];
        const float4 d = red[270 + tid];
        float4 s;
        s.x = ((a.x + b1.x) + c.x) + d.x;
        s.y = ((a.y + b1.y) + c.y) + d.y;
        s.z = ((a.z + b1.z) + c.z) + d.z;
        s.w = ((a.w + b1.w) + c.w) + d.w;
        g_partial4[b][chunk][tid] = s;
    }
}

// ---------------------------------------------------------------------------
// K2: per-batch reduce (32 chunks, double, fixed order) + bitonic sort of 512
// with one element per thread (shfl for j<32: 35 of 45 phases barrier-free).
// Key order: value desc, index asc (jax.lax.top_k semantics).
// Also writes the two cls rows of the output. grid (B), 512 threads.
// ---------------------------------------------------------------------------
__global__ void topk_kernel(const float* __restrict__ cls,
                            float* __restrict__ out) {
    const int b   = blockIdx.x;
    const int tid = threadIdx.x;

    __shared__ double sv[512];
    __shared__ int    si[512];

    double v;
    int    idx = tid;
    if (tid < HW_) {
        const float* gp = (const float*)&g_partial4[b][0][0];
        double s = 0.0;
#pragma unroll 8
        for (int j = 0; j < CHUNKS; ++j) s += (double)gp[j * HW_ + tid];
        v = s;
    } else {
        v = -1e300;
    }

    for (int k = 2; k <= 512; k <<= 1) {
        const bool up = ((tid & k) == 0);
        int j = k >> 1;
        for (; j >= 32; j >>= 1) {
            sv[tid] = v; si[tid] = idx;
            __syncthreads();
            const double pv = sv[tid ^ j];
            const int    pi = si[tid ^ j];
            __syncthreads();
            const bool iLess = (v > pv) || (v == pv && idx < pi);
            const bool lower = ((tid & j) == 0);
            const bool keepOwn = lower ? (up ? iLess : !iLess)
                                       : (up ? !iLess : iLess);
            if (!keepOwn) { v = pv; idx = pi; }
        }
        for (; j >= 1; j >>= 1) {
            const double pv = __shfl_xor_sync(0xffffffffu, v, j);
            const int    pi = __shfl_xor_sync(0xffffffffu, idx, j);
            const bool iLess = (v > pv) || (v == pv && idx < pi);
            const bool lower = ((tid & j) == 0);
            const bool keepOwn = lower ? (up ? iLess : !iLess)
                                       : (up ? !iLess : iLess);
            if (!keepOwn) { v = pv; idx = pi; }
        }
    }

    if (tid < K_) g_topk[b][tid] = idx;

    // cls rows via float4: row 0 = cls[b,0,:], row 121 = cls[b,1,:]
    {
        const float4* c4 = (const float4*)(cls + (size_t)b * T_ * C_);
        float4* o4 = (float4*)(out + (size_t)b * ROWS_ * C_);
        if (tid < 256)
            o4[tid] = c4[tid];                            // row 0
        else
            o4[(size_t)121 * (C_ / 4) + (tid - 256)] = c4[(C_ / 4) + (tid - 256)]; // row 121
    }
}

// ---------------------------------------------------------------------------
// K3: gather of the 120 selected t=0 tokens.
// grid (16 ctiles of 64 ch, B), block (32,8).
// Tokens along lanes: each warp-LDG reads 32 token positions inside ONE
// 1440-byte channel row (<=12 lines, L1-cached across token groups), so each
// channel row's lines are fetched once per block. All reads L2-resident
// (t=0 slice streamed by K1). smem pitch 65 -> conflict-free both phases.
// Writes: out[b, 1+tok, c] coalesced 128B per warp-store.
// ---------------------------------------------------------------------------
__global__ void gather_kernel(const float* __restrict__ x,
                              float* __restrict__ out) {
    const int c0 = blockIdx.x * 64;
    const int b  = blockIdx.y;
    const int tx = threadIdx.x;          // 0..31
    const int ty = threadIdx.y;          // 0..7
    const int tid = ty * 32 + tx;

    __shared__ float g[120][65];
    __shared__ int   pidx[128];

    for (int i = tid; i < K_; i += 256)
        pidx[i] = g_topk[b][i];
    __syncthreads();

    // load phase: token groups of 32 along lanes, channels along ty+8*cg
#pragma unroll
    for (int tg = 0; tg < 4; ++tg) {
        const int tok = tg * 32 + tx;
        const bool valid = (tok < K_);
        const int p = valid ? pidx[tok] : 0;
#pragma unroll
        for (int cg = 0; cg < 8; ++cg) {
            const int c = ty + 8 * cg;   // 0..63
            if (valid)
                g[tok][c] = x[((size_t)(b * C_ + c0 + c)) * STRIDE_T + p]; // t=0
        }
    }
    __syncthreads();

    // write phase: warp ty owns tokens ty, ty+8, ... ; lanes sweep channels
    for (int tok = ty; tok < K_; tok += 8) {
        float* orow = out + ((size_t)b * ROWS_ + 1 + tok) * C_ + c0;
        orow[tx]      = g[tok][tx];
        orow[32 + tx] = g[tok][32 + tx];
    }
}

// ---------------------------------------------------------------------------
// K4: t=1 slice transpose -> out rows 122..481.
// grid (8 ctiles of 128 ch, 12 ptiles, B), block 256.
// float4 coalesced loads along p, smem transpose (pitch 132, 16B-aligned
// rows), float4 coalesced stores along c.
// ---------------------------------------------------------------------------
__global__ void t1copy_kernel(const float* __restrict__ x,
                              float* __restrict__ out) {
    const int ct  = blockIdx.x;          // 0..7  (128 channels each)
    const int pt  = blockIdx.y;          // 0..11
    const int b   = blockIdx.z;
    const int tid = threadIdx.x;         // 0..255
    const int c0  = ct * 128;
    const int lane = tid & 31;
    const int w    = tid >> 5;           // 0..7

    __shared__ __align__(16) float tile[32][132];

    const int p0 = pt * 32;              // 0,32,...,352 (last tile partial)
    const int p4 = tid & 7;              // float4 index along p
    const int cb = tid >> 3;             // 0..31
#pragma unroll
    for (int i = 0; i < 4; ++i) {
        const int cl = cb + 32 * i;      // 0..127
        const float4 val = *(const float4*)&x[((size_t)(b * C_ + c0 + cl)) * STRIDE_T
                                              + HW_ + p0 + 4 * p4];
        tile[4 * p4 + 0][cl] = val.x;
        tile[4 * p4 + 1][cl] = val.y;
        tile[4 * p4 + 2][cl] = val.z;
        tile[4 * p4 + 3][cl] = val.w;
    }
    __syncthreads();

#pragma unroll
    for (int i = 0; i < 4; ++i) {
        const int plocal = w + 8 * i;    // 0..31
        const int pr = p0 + plocal;
        if (pr < HW_) {
            const float4 val = *(const float4*)&tile[plocal][4 * lane];
            *(float4*)&out[((size_t)b * ROWS_ + 122 + pr) * C_ + c0 + 4 * lane] = val;
        }
    }
}

// ---------------------------------------------------------------------------
extern "C" void kernel_launch(void* const* d_in, const int* in_sizes, int n_in,
                              void* d_out, int out_size) {
    const float* x   = (const float*)d_in[0];
    const float* cls = (const float*)d_in[1];
    // Defensive: x is the huge tensor (94,371,840 elems), cls is 262,144.
    if (n_in >= 2 && in_sizes[0] < in_sizes[1]) {
        const float* tmp = x; x = cls; cls = tmp;
    }
    float* out = (float*)d_out;

    scores_kernel <<<dim3(CHUNKS, B_), 384>>>(x, cls);
    topk_kernel   <<<B_, 512>>>(cls, out);
    gather_kernel <<<dim3(16, B_), dim3(32, 8)>>>(x, out);
    t1copy_kernel <<<dim3(8, 12, B_), 256>>>(x, out);
}